// round 4
// baseline (speedup 1.0000x reference)
#include <cuda_runtime.h>
#include <math.h>

#define BATCH 2
#define CIN   256
#define CHID  128
#define TT    128     // tscale
#define NSMP  32      // num_sample
#define CROI  512
#define COUT  128
#define DSC   128     // dscale
#define BO    (BATCH*CROI)   // 1024
#define NDM   (DSC*TT)       // 16384

// Scratch
__device__ float g_h[BATCH*CHID*TT];            // h[b][c][t]
__device__ float g_w3dT[NSMP*CROI*CHID];        // w3dT[n][o][c]
__device__ float g_P[(size_t)NSMP*TT*BO];       // P[n][t][bo], bo = b*512+o
__device__ float g_M3[(size_t)BO*NDM];          // m3[bo][d*128+m]

// ---------------------------------------------------------------------------
// K1: conv1d(256->128, k=3, pad=1) + bias + ReLU
// ---------------------------------------------------------------------------
__global__ __launch_bounds__(128) void conv1d_kernel(
    const float* __restrict__ x, const float* __restrict__ w,
    const float* __restrict__ bias)
{
    int bo = blockIdx.x;
    int b = bo >> 7, o = bo & 127;
    int t = threadIdx.x;
    __shared__ float ws[CIN*3];
    for (int idx = t; idx < CIN*3; idx += 128) ws[idx] = w[o*CIN*3 + idx];
    __syncthreads();
    const float* xb = x + (size_t)b*CIN*TT;
    float acc = bias[o];
    #pragma unroll 4
    for (int i = 0; i < CIN; ++i) {
        float xm = (t > 0)    ? xb[i*TT + t - 1] : 0.f;
        float xc =              xb[i*TT + t];
        float xp = (t < TT-1) ? xb[i*TT + t + 1] : 0.f;
        acc = fmaf(xm, ws[i*3+0], acc);
        acc = fmaf(xc, ws[i*3+1], acc);
        acc = fmaf(xp, ws[i*3+2], acc);
    }
    g_h[(b*CHID + o)*TT + t] = fmaxf(acc, 0.f);
}

// ---------------------------------------------------------------------------
// K2a: transpose w3d[o][c][n] -> g_w3dT[n][o][c]
// ---------------------------------------------------------------------------
__global__ __launch_bounds__(256) void w3d_transpose_kernel(
    const float* __restrict__ w3d)
{
    int o  = blockIdx.x;
    int c0 = blockIdx.y * 32;
    __shared__ float tile[32][33];
    int tn = threadIdx.x & 31;
    int tg = threadIdx.x >> 5;
    for (int cc = tg; cc < 32; cc += 8)
        tile[cc][tn] = w3d[((size_t)(o*CHID + c0 + cc))*NSMP + tn];
    __syncthreads();
    int tc = threadIdx.x & 31;
    for (int nn = tg; nn < 32; nn += 8)
        g_w3dT[((size_t)(nn*CROI + o))*CHID + c0 + tc] = tile[tc][nn];
}

// ---------------------------------------------------------------------------
// K2b: P[n][t][b*512+o] = sum_c w3dT[n][o][c] * h[b][c][t]
// ---------------------------------------------------------------------------
__global__ __launch_bounds__(256) void pmat_kernel()
{
    int o0 = blockIdx.x * 128;
    int n  = blockIdx.y;
    int b  = blockIdx.z;
    __shared__ float As[16][132];
    __shared__ float Bs[16][128];
    const float* A  = g_w3dT + (size_t)(n*CROI + o0)*CHID;
    const float* Bm = g_h + (size_t)b*CHID*TT;
    int tid = threadIdx.x;
    int ty = tid >> 4, tx = tid & 15;
    float acc[8][8];
    #pragma unroll
    for (int i = 0; i < 8; ++i)
        #pragma unroll
        for (int j = 0; j < 8; ++j) acc[i][j] = 0.f;

    for (int c0 = 0; c0 < CHID; c0 += 16) {
        {
            int r  = tid >> 2;
            int c4 = (tid & 3) * 4;
            #pragma unroll
            for (int p = 0; p < 2; ++p) {
                float4 v = *(const float4*)&A[(r + 64*p)*CHID + c0 + c4];
                As[c4+0][r+64*p] = v.x;
                As[c4+1][r+64*p] = v.y;
                As[c4+2][r+64*p] = v.z;
                As[c4+3][r+64*p] = v.w;
            }
        }
        {
            int r  = tid >> 5;
            int c4 = (tid & 31) * 4;
            #pragma unroll
            for (int p = 0; p < 2; ++p) {
                float4 v = *(const float4*)&Bm[(c0 + r + 8*p)*TT + c4];
                *(float4*)&Bs[r + 8*p][c4] = v;
            }
        }
        __syncthreads();
        #pragma unroll
        for (int kk = 0; kk < 16; ++kk) {
            float4 a0 = *(const float4*)&As[kk][ty*8];
            float4 a1 = *(const float4*)&As[kk][ty*8+4];
            float4 b0 = *(const float4*)&Bs[kk][tx*8];
            float4 b1 = *(const float4*)&Bs[kk][tx*8+4];
            float av[8] = {a0.x,a0.y,a0.z,a0.w,a1.x,a1.y,a1.z,a1.w};
            float bv[8] = {b0.x,b0.y,b0.z,b0.w,b1.x,b1.y,b1.z,b1.w};
            #pragma unroll
            for (int i = 0; i < 8; ++i)
                #pragma unroll
                for (int j = 0; j < 8; ++j)
                    acc[i][j] = fmaf(av[i], bv[j], acc[i][j]);
        }
        __syncthreads();
    }
    #pragma unroll
    for (int j = 0; j < 8; ++j) {
        int t = tx*8 + j;
        size_t base = ((size_t)(n*TT + t))*BO + b*CROI + o0;
        #pragma unroll
        for (int i = 0; i < 8; ++i)
            g_P[base + ty*8 + i] = acc[i][j];
    }
}

// ---------------------------------------------------------------------------
// K3: convolution-form interp.
// Per n, the 3 taps collapse to an 8-wide conv kernel wv[n][0..7] (weights /3
// folded). out[m] = sum_r wv[r] * P[n][t0base[n] + m + r][bo], rows outside
// [0,128) are zero. Boundary (s in [-1,0), trunc semantics) fixed by exact
// per-column fp64 correction cw * P[n][0][bo] at column mj.
// Grid: x = m-tile of 64 (2), y = d (128), z = bo-tile (8). 256 threads.
// Thread: warp mg (tid>>5) owns m-cols mg*8..+7; lane bl owns 4 bo (4*bl).
// Window = 15 float4 registers via predicated coalesced LDG.128; no barriers
// in the mainloop.
// ---------------------------------------------------------------------------
#define SPAD 129
__global__ __launch_bounds__(256) void interp_kernel(const float* __restrict__ b3d)
{
    int m0  = blockIdx.x * 64;
    int d   = blockIdx.y;
    int bo0 = blockIdx.z * 128;
    int tid = threadIdx.x;

    // -------- fully invalid tile: relu(bias) fill --------
    if (m0 >= TT - d) {
        int f4 = tid & 15;                 // 16 float4 per row of 64 cols
        int r0 = tid >> 4;                 // 16 rows per pass
        #pragma unroll
        for (int k = 0; k < 8; ++k) {
            int r = r0 + 16*k;
            float v = fmaxf(b3d[(bo0 + r) & 511], 0.f);
            float4 vv = make_float4(v, v, v, v);
            *(float4*)&g_M3[(size_t)(bo0 + r)*NDM + d*TT + m0 + f4*4] = vv;
        }
        return;
    }

    __shared__ float s_wv[NSMP][8];
    __shared__ int   s_t0b[NSMP];
    __shared__ int   s_mj[96];
    __shared__ float s_cw[96];
    __shared__ float stage[64*SPAD];       // transpose stage [m][bo] stride 129

    // -------- build conv weights + boundary-correction tables (fp64) -----
    ((float*)s_wv)[tid] = 0.f;             // 256 entries zeroed
    __syncthreads();
    if (tid < NSMP) {
        int n = tid;
        double h = 0.5 * (double)(d + 1);
        double p = (2.0*(double)d + 1.0) / 95.0;
        int t0b = 0;
        #pragma unroll
        for (int j = 0; j < 3; ++j) {
            int i = 3*n + j;
            double q = p * (double)i;
            double s = ((double)m0 - h) + q;        // numpy op order
            double fs = floor(s);
            int t0 = (int)fs;
            float f = (float)(s - fs);
            if (j == 0) { t0b = t0; s_t0b[n] = t0; }
            int dlt = t0 - t0b;                     // 0..6
            s_wv[n][dlt]   += (1.0f - f) * (1.0f/3.0f);
            s_wv[n][dlt+1] += f * (1.0f/3.0f);
            int mj = -1 - t0;                       // column with s in [-1,0)
            float cw = 0.f;
            if (mj >= 0 && mj < 64) {
                double ss = ((double)(m0 + mj) - h) + q;  // that column's fp64
                cw = (((ss > -1.0) ? 1.0f : 0.0f) - f) * (1.0f/3.0f);
            } else mj = -1;
            s_mj[i] = mj;
            s_cw[i] = cw;
        }
    }
    __syncthreads();

    int bl = tid & 31;     // lane: 4 bo
    int mg = tid >> 5;     // warp: 8 m-cols, m_local = mg*8..mg*8+7
    float4 acc[8];
    #pragma unroll
    for (int c = 0; c < 8; ++c) acc[c] = make_float4(0,0,0,0);

    const float* lane_base = g_P + bo0 + 4*bl;

    for (int n = 0; n < NSMP; ++n) {
        int   t0b   = s_t0b[n];
        const float* plane = lane_base + (size_t)n*TT*BO;
        int   rbase = t0b + mg*8;

        // window: 15 rows -> registers (predicated, coalesced 512B/warp)
        float4 w[15];
        #pragma unroll
        for (int k = 0; k < 15; ++k) {
            int t = rbase + k;
            float4 v = make_float4(0,0,0,0);
            if ((unsigned)t < (unsigned)TT)
                v = *(const float4*)(plane + (size_t)t*BO);
            w[k] = v;
        }
        float wv[8];
        #pragma unroll
        for (int r = 0; r < 8; ++r) wv[r] = s_wv[n][r];   // smem broadcast

        #pragma unroll
        for (int r = 0; r < 8; ++r) {
            float c = wv[r];
            #pragma unroll
            for (int cc = 0; cc < 8; ++cc) {
                acc[cc].x = fmaf(c, w[cc+r].x, acc[cc].x);
                acc[cc].y = fmaf(c, w[cc+r].y, acc[cc].y);
                acc[cc].z = fmaf(c, w[cc+r].z, acc[cc].z);
                acc[cc].w = fmaf(c, w[cc+r].w, acc[cc].w);
            }
        }

        // boundary corrections (warp-uniform branch; row 0 always valid)
        #pragma unroll
        for (int j = 0; j < 3; ++j) {
            int cc = s_mj[3*n + j] - mg*8;
            if ((unsigned)cc < 8u) {
                float cw = s_cw[3*n + j];
                float4 r0 = *(const float4*)plane;
                acc[cc].x = fmaf(cw, r0.x, acc[cc].x);
                acc[cc].y = fmaf(cw, r0.y, acc[cc].y);
                acc[cc].z = fmaf(cw, r0.z, acc[cc].z);
                acc[cc].w = fmaf(cw, r0.w, acc[cc].w);
            }
        }
    }

    // -------- transpose via smem (conflict-free stride 129), bias+relu ----
    #pragma unroll
    for (int cc = 0; cc < 8; ++cc) {
        float* s = &stage[(mg*8 + cc)*SPAD + 4*bl];
        s[0] = acc[cc].x; s[1] = acc[cc].y; s[2] = acc[cc].z; s[3] = acc[cc].w;
    }
    __syncthreads();

    int warp = tid >> 5, lane = tid & 31;
    int vlim = TT - 1 - d - m0;            // col m valid iff m <= vlim
    #pragma unroll
    for (int rr = 0; rr < 16; ++rr) {
        int r = warp*16 + rr;              // bo row 0..127
        float bias = b3d[(bo0 + r) & 511];
        size_t base = (size_t)(bo0 + r)*NDM + d*TT + m0;
        #pragma unroll
        for (int hh = 0; hh < 2; ++hh) {
            int m = lane + 32*hh;
            float v = stage[m*SPAD + r] + bias;
            v = (m <= vlim) ? fmaxf(v, 0.f) : fmaxf(bias, 0.f);
            g_M3[base + m] = v;
        }
    }
}

// ---------------------------------------------------------------------------
// K4: out[b][o2][dm] = relu( b2d[o2] + sum_o w2d[o2][o] * M3[b*512+o][dm] )
// 128x128 tile, 8x8 micro, K=512.
// ---------------------------------------------------------------------------
__global__ __launch_bounds__(256) void out_gemm_kernel(
    const float* __restrict__ w2d, const float* __restrict__ b2d,
    float* __restrict__ out)
{
    int dm0 = blockIdx.x * 128;
    int b   = blockIdx.y;
    __shared__ float As[16][132];
    __shared__ float Bs[16][132];
    int tid = threadIdx.x;
    int ty = tid >> 4, tx = tid & 15;
    float acc[8][8];
    #pragma unroll
    for (int i = 0; i < 8; ++i)
        #pragma unroll
        for (int j = 0; j < 8; ++j) acc[i][j] = 0.f;

    for (int k0 = 0; k0 < CROI; k0 += 16) {
        {   // A: w2d[o2][k] -> As[k][o2], 128 x 16
            int r  = tid >> 2;
            int c4 = (tid & 3) * 4;
            #pragma unroll
            for (int p = 0; p < 2; ++p) {
                float4 v = *(const float4*)&w2d[(size_t)(r + 64*p)*CROI + k0 + c4];
                As[c4+0][r+64*p] = v.x;
                As[c4+1][r+64*p] = v.y;
                As[c4+2][r+64*p] = v.z;
                As[c4+3][r+64*p] = v.w;
            }
        }
        {   // B: M3 rows b*512+k0..+15, cols dm0..+127
            int kk = tid >> 4;
            int j4 = (tid & 15) * 4;
            #pragma unroll
            for (int p = 0; p < 2; ++p) {
                float4 v = *(const float4*)&g_M3[(size_t)(b*CROI + k0 + kk)*NDM + dm0 + j4 + 64*p];
                *(float4*)&Bs[kk][j4 + 64*p] = v;
            }
        }
        __syncthreads();
        #pragma unroll
        for (int kk = 0; kk < 16; ++kk) {
            float4 a0 = *(const float4*)&As[kk][ty*8];
            float4 a1 = *(const float4*)&As[kk][ty*8+4];
            float4 b0 = *(const float4*)&Bs[kk][tx*8];
            float4 b1 = *(const float4*)&Bs[kk][tx*8+4];
            float av[8] = {a0.x,a0.y,a0.z,a0.w,a1.x,a1.y,a1.z,a1.w};
            float bv[8] = {b0.x,b0.y,b0.z,b0.w,b1.x,b1.y,b1.z,b1.w};
            #pragma unroll
            for (int i = 0; i < 8; ++i)
                #pragma unroll
                for (int j = 0; j < 8; ++j)
                    acc[i][j] = fmaf(av[i], bv[j], acc[i][j]);
        }
        __syncthreads();
    }
    #pragma unroll
    for (int i = 0; i < 8; ++i) {
        int o2 = ty*8 + i;
        float bias = b2d[o2];
        size_t base = (size_t)(b*COUT + o2)*NDM + dm0 + tx*8;
        #pragma unroll
        for (int j = 0; j < 8; ++j)
            out[base + j] = fmaxf(acc[i][j] + bias, 0.f);
    }
}

// ---------------------------------------------------------------------------
// Inputs: 0:x 1:w_red 2:b_red 3:w3d 4:b3d 5:w2d 6:b2d 7:sample_mask (unused)
// ---------------------------------------------------------------------------
extern "C" void kernel_launch(void* const* d_in, const int* in_sizes, int n_in,
                              void* d_out, int out_size)
{
    const float* x     = (const float*)d_in[0];
    const float* w_red = (const float*)d_in[1];
    const float* b_red = (const float*)d_in[2];
    const float* w3d   = (const float*)d_in[3];
    const float* b3d   = (const float*)d_in[4];
    const float* w2d   = (const float*)d_in[5];
    const float* b2d   = (const float*)d_in[6];
    float* out = (float*)d_out;

    conv1d_kernel<<<BATCH*CHID, 128>>>(x, w_red, b_red);
    w3d_transpose_kernel<<<dim3(CROI, 4), 256>>>(w3d);
    pmat_kernel<<<dim3(4, NSMP, BATCH), 256>>>();
    interp_kernel<<<dim3(2, DSC, BO/128), 256>>>(b3d);
    out_gemm_kernel<<<dim3(NDM/128, BATCH), 256>>>(w2d, b2d, out);
}